// round 1
// baseline (speedup 1.0000x reference)
#include <cuda_runtime.h>
#include <mma.h>

using namespace nvcuda;

// Problem constants (fixed by reference)
#define Bc 4
#define Hc 16
#define Sc 2048
#define Dc 128

// Tiling
#define TQ 64
#define TK 64
#define THREADS 256
#define QLD 136   // row stride (floats) for Q/K/V smem tiles (128 + 8 pad)
#define PLD 72    // row stride for P tile (64 + 8 pad)

// smem layout (floats): Qs[64*136] Ks[64*136] Vs[64*136] Ps[64*72] lrow[64]
#define SMEM_FLOATS (3 * TQ * QLD + TQ * PLD + TQ)
#define SMEM_BYTES (SMEM_FLOATS * 4)

__global__ __launch_bounds__(THREADS, 1)
void attn_main_kernel(const float* __restrict__ qg,
                      const float* __restrict__ kg,
                      const float* __restrict__ vg,
                      const float* __restrict__ mg,
                      float* __restrict__ outg,
                      float* __restrict__ attng) {
    extern __shared__ float sm[];
    float* Qs   = sm;
    float* Ks   = Qs + TQ * QLD;
    float* Vs   = Ks + TK * QLD;
    float* Ps   = Vs + TK * QLD;
    float* lrow = Ps + TQ * PLD;

    const int h  = blockIdx.x;   // fastest: mask slice reused across heads via L2
    const int qt = blockIdx.y;
    const int b  = blockIdx.z;
    const int tid  = threadIdx.x;
    const int warp = tid >> 5;
    const int q0   = qt * TQ;

    const long long bh = (long long)b * Hc + h;
    const float* qptr = qg + (bh * Sc + q0) * (long long)Dc;
    const float* kbase = kg + bh * Sc * (long long)Dc;
    const float* vbase = vg + bh * Sc * (long long)Dc;
    const float* mbase = mg + ((long long)b * Sc + q0) * (long long)Sc;
    float* attnbase = attng ? (attng + (bh * Sc + q0) * (long long)Sc) : nullptr;

    // Load Q tile (64 x 128) into smem
    for (int idx = tid * 4; idx < TQ * Dc; idx += THREADS * 4) {
        int r = idx >> 7, c = idx & 127;
        float4 val = *(const float4*)(qptr + (long long)r * Dc + c);
        *(float4*)(Qs + r * QLD + c) = val;
    }
    if (tid < TQ) lrow[tid] = 0.0f;

    // Persistent PV accumulators: warp -> row tile ti, col tiles jb..jb+3
    const int ti  = warp >> 1;         // 0..3 (16-row tile of the 64 queries)
    const int tj2 = (warp & 1) * 2;    // scores col tiles: tj2, tj2+1
    const int jb  = (warp & 1) * 4;    // PV col tiles: jb..jb+3 (of 8)

    wmma::fragment<wmma::accumulator, 16, 16, 8, float> Oacc[4];
    #pragma unroll
    for (int j = 0; j < 4; ++j) wmma::fill_fragment(Oacc[j], 0.0f);

    __syncthreads();

    for (int kt = 0; kt < Sc / TK; ++kt) {
        __syncthreads();  // previous iteration's PV reads of Ks/Vs/Ps complete

        // Load K,V tiles (64 x 128 each)
        const float* kp = kbase + (long long)kt * TK * Dc;
        const float* vp = vbase + (long long)kt * TK * Dc;
        for (int idx = tid * 4; idx < TK * Dc; idx += THREADS * 4) {
            int r = idx >> 7, c = idx & 127;
            *(float4*)(Ks + r * QLD + c) = *(const float4*)(kp + (long long)r * Dc + c);
            *(float4*)(Vs + r * QLD + c) = *(const float4*)(vp + (long long)r * Dc + c);
        }
        __syncthreads();

        // ---- Scores: S = Q * K^T (tf32 wmma), raw dot products ----
        wmma::fragment<wmma::accumulator, 16, 16, 8, float> Sacc[2];
        wmma::fill_fragment(Sacc[0], 0.0f);
        wmma::fill_fragment(Sacc[1], 0.0f);
        #pragma unroll 4
        for (int k8 = 0; k8 < Dc / 8; ++k8) {
            wmma::fragment<wmma::matrix_a, 16, 16, 8, wmma::precision::tf32, wmma::row_major> af;
            wmma::load_matrix_sync(af, Qs + ti * 16 * QLD + k8 * 8, QLD);
            #pragma unroll
            for (int e = 0; e < af.num_elements; ++e) af.x[e] = wmma::__float_to_tf32(af.x[e]);
            #pragma unroll
            for (int jj = 0; jj < 2; ++jj) {
                wmma::fragment<wmma::matrix_b, 16, 16, 8, wmma::precision::tf32, wmma::col_major> bf;
                wmma::load_matrix_sync(bf, Ks + (tj2 + jj) * 16 * QLD + k8 * 8, QLD);
                #pragma unroll
                for (int e = 0; e < bf.num_elements; ++e) bf.x[e] = wmma::__float_to_tf32(bf.x[e]);
                wmma::mma_sync(Sacc[jj], af, bf, Sacc[jj]);
            }
        }
        wmma::store_matrix_sync(Ps + ti * 16 * PLD + tj2 * 16, Sacc[0], PLD, wmma::mem_row_major);
        wmma::store_matrix_sync(Ps + ti * 16 * PLD + (tj2 + 1) * 16, Sacc[1], PLD, wmma::mem_row_major);
        __syncthreads();

        // ---- Elementwise: p = mask ? 0 : exp(s/128); write attn; rowsum ----
        {
            const int r  = tid >> 2;           // query row within tile
            const int c0 = (tid & 3) * 16;     // 16-col segment
            const float* mrow = mbase + (long long)r * Sc + kt * TK;
            float lsum = 0.0f;
            #pragma unroll
            for (int cc = 0; cc < 4; ++cc) {
                int c = c0 + cc * 4;
                float4 s4 = *(float4*)(Ps + r * PLD + c);
                float4 m4 = *(const float4*)(mrow + c);
                float4 p;
                p.x = (m4.x != 0.0f) ? 0.0f : __expf(s4.x * 0.0078125f);
                p.y = (m4.y != 0.0f) ? 0.0f : __expf(s4.y * 0.0078125f);
                p.z = (m4.z != 0.0f) ? 0.0f : __expf(s4.z * 0.0078125f);
                p.w = (m4.w != 0.0f) ? 0.0f : __expf(s4.w * 0.0078125f);
                *(float4*)(Ps + r * PLD + c) = p;
                if (attnbase)
                    *(float4*)(attnbase + (long long)r * Sc + kt * TK + c) = p;
                lsum += p.x + p.y + p.z + p.w;
            }
            // 4 lanes per row -> tree reduce, lane (tid&3)==0 accumulates
            lsum += __shfl_xor_sync(0xffffffffu, lsum, 1);
            lsum += __shfl_xor_sync(0xffffffffu, lsum, 2);
            if ((tid & 3) == 0) lrow[r] += lsum;
        }
        __syncthreads();

        // ---- PV: O += P * V (tf32 wmma) ----
        #pragma unroll 2
        for (int k8 = 0; k8 < TK / 8; ++k8) {
            wmma::fragment<wmma::matrix_a, 16, 16, 8, wmma::precision::tf32, wmma::row_major> af;
            wmma::load_matrix_sync(af, Ps + ti * 16 * PLD + k8 * 8, PLD);
            #pragma unroll
            for (int e = 0; e < af.num_elements; ++e) af.x[e] = wmma::__float_to_tf32(af.x[e]);
            #pragma unroll
            for (int jj = 0; jj < 4; ++jj) {
                wmma::fragment<wmma::matrix_b, 16, 16, 8, wmma::precision::tf32, wmma::row_major> bf;
                wmma::load_matrix_sync(bf, Vs + k8 * 8 * QLD + (jb + jj) * 16, QLD);
                #pragma unroll
                for (int e = 0; e < bf.num_elements; ++e) bf.x[e] = wmma::__float_to_tf32(bf.x[e]);
                wmma::mma_sync(Oacc[jj], af, bf, Oacc[jj]);
            }
        }
    }

    __syncthreads();
    // Stage O into smem (reuse Qs), then scaled write to gmem
    #pragma unroll
    for (int jj = 0; jj < 4; ++jj)
        wmma::store_matrix_sync(Qs + ti * 16 * QLD + (jb + jj) * 16, Oacc[jj], QLD,
                                wmma::mem_row_major);
    __syncthreads();

    {
        const int r  = tid >> 2;
        const int c0 = (tid & 3) * 32;
        const float inv = 1.0f / lrow[r];
        float* orow = outg + (bh * Sc + q0 + r) * (long long)Dc;
        #pragma unroll
        for (int cc = 0; cc < 8; ++cc) {
            int c = c0 + cc * 4;
            float4 o4 = *(float4*)(Qs + r * QLD + c);
            o4.x *= inv; o4.y *= inv; o4.z *= inv; o4.w *= inv;
            *(float4*)(orow + c) = o4;
        }
    }
}

// Kernel 2: normalize each attn row in place (re-derives the row sum).
__global__ __launch_bounds__(256, 8)
void attn_norm_kernel(float* __restrict__ attn) {
    const long long row = blockIdx.x;
    float4* rp = (float4*)(attn + row * (long long)Sc);
    const int t = threadIdx.x;

    float4 a = rp[t];
    float4 b = rp[t + 256];
    float s = a.x + a.y + a.z + a.w + b.x + b.y + b.z + b.w;
    #pragma unroll
    for (int o = 16; o > 0; o >>= 1) s += __shfl_xor_sync(0xffffffffu, s, o);

    __shared__ float red[8];
    if ((t & 31) == 0) red[t >> 5] = s;
    __syncthreads();
    float tot = red[0] + red[1] + red[2] + red[3] + red[4] + red[5] + red[6] + red[7];
    float inv = 1.0f / tot;

    a.x *= inv; a.y *= inv; a.z *= inv; a.w *= inv;
    b.x *= inv; b.y *= inv; b.z *= inv; b.w *= inv;
    rp[t] = a;
    rp[t + 256] = b;
}

extern "C" void kernel_launch(void* const* d_in, const int* in_sizes, int n_in,
                              void* d_out, int out_size) {
    const float* q = (const float*)d_in[0];
    const float* k = (const float*)d_in[1];
    const float* v = (const float*)d_in[2];
    const float* m = (const float*)d_in[3];
    float* out = (float*)d_out;

    const long long OUT_ELE = (long long)Bc * Hc * Sc * Dc;  // 16,777,216
    float* attn = ((long long)out_size > OUT_ELE) ? (out + OUT_ELE) : nullptr;

    cudaFuncSetAttribute(attn_main_kernel,
                         cudaFuncAttributeMaxDynamicSharedMemorySize, SMEM_BYTES);

    dim3 grid1(Hc, Sc / TQ, Bc);  // h fastest -> mask L2 reuse across heads
    attn_main_kernel<<<grid1, THREADS, SMEM_BYTES>>>(q, k, v, m, out, attn);

    if (attn) {
        attn_norm_kernel<<<(long long)Bc * Hc * Sc, 256>>>(attn);
    }
}

// round 2
// speedup vs baseline: 1.2166x; 1.2166x over previous
#include <cuda_runtime.h>
#include <mma.h>

using namespace nvcuda;

// Problem constants (fixed by reference)
#define Bc 4
#define Hc 16
#define Sc 2048
#define Dc 128

// Tiling
#define TQ 64
#define TK 64
#define THREADS 256
#define QLD 136   // row stride (floats) for Q/K/V smem tiles (128 + 8 pad)
#define PLD 72    // row stride for P tile (64 + 8 pad)

// smem (floats): Qs[64*136]  Ks[2][64*136]  Vs[2][64*136]  Ps[64*72]  lrow[64]
#define TILE_F (TQ * QLD)
#define SMEM_FLOATS (5 * TILE_F + TQ * PLD + TQ)
#define SMEM_BYTES (SMEM_FLOATS * 4)

__device__ __forceinline__ void cp_async16(float* smem_dst, const float* gmem_src) {
    unsigned saddr = (unsigned)__cvta_generic_to_shared(smem_dst);
    asm volatile("cp.async.cg.shared.global [%0], [%1], 16;\n" ::"r"(saddr), "l"(gmem_src));
}
__device__ __forceinline__ void cp_commit() {
    asm volatile("cp.async.commit_group;\n");
}
__device__ __forceinline__ void cp_wait_all() {
    asm volatile("cp.async.wait_group 0;\n");
}

__global__ __launch_bounds__(THREADS, 1)
void attn_main_kernel(const float* __restrict__ qg,
                      const float* __restrict__ kg,
                      const float* __restrict__ vg,
                      const float* __restrict__ mg,
                      float* __restrict__ outg,
                      float* __restrict__ attng) {
    extern __shared__ float sm[];
    float* Qs   = sm;                       // [64 x 136]
    float* Ks   = Qs + TILE_F;              // [2][64 x 136]
    float* Vs   = Ks + 2 * TILE_F;          // [2][64 x 136]
    float* Ps   = Vs + 2 * TILE_F;          // [64 x 72]
    float* lrow = Ps + TQ * PLD;            // [64]

    const int h  = blockIdx.x;   // fastest: mask slice reused across heads via L2
    const int qt = blockIdx.y;
    const int b  = blockIdx.z;
    const int tid  = threadIdx.x;
    const int warp = tid >> 5;
    const int q0   = qt * TQ;

    const long long bh = (long long)b * Hc + h;
    const float* qptr  = qg + (bh * Sc + q0) * (long long)Dc;
    const float* kbase = kg + bh * Sc * (long long)Dc;
    const float* vbase = vg + bh * Sc * (long long)Dc;
    const float* mbase = mg + ((long long)b * Sc + q0) * (long long)Sc;
    float* attnbase = attng ? (attng + (bh * Sc + q0) * (long long)Sc) : nullptr;

    // Load Q tile (64 x 128), pre-rounded to tf32 so fragments need no conversion
    for (int idx = tid * 4; idx < TQ * Dc; idx += THREADS * 4) {
        int r = idx >> 7, c = idx & 127;
        float4 val = *(const float4*)(qptr + (long long)r * Dc + c);
        val.x = wmma::__float_to_tf32(val.x);
        val.y = wmma::__float_to_tf32(val.y);
        val.z = wmma::__float_to_tf32(val.z);
        val.w = wmma::__float_to_tf32(val.w);
        *(float4*)(Qs + r * QLD + c) = val;
    }
    if (tid < TQ) lrow[tid] = 0.0f;

    // Persistent PV accumulators: warp -> row tile ti, col tiles jb..jb+3
    const int ti  = warp >> 1;         // 0..3 (16-row tile of the 64 queries)
    const int tj2 = (warp & 1) * 2;    // scores col tiles: tj2, tj2+1
    const int jb  = (warp & 1) * 4;    // PV col tiles: jb..jb+3 (of 8)

    wmma::fragment<wmma::accumulator, 16, 16, 8, float> Oacc[4];
    #pragma unroll
    for (int j = 0; j < 4; ++j) wmma::fill_fragment(Oacc[j], 0.0f);

    // ---- Prologue: async prefetch of K/V tile 0 into buffer 0 ----
    {
        const float* kp = kbase;
        const float* vp = vbase;
        #pragma unroll
        for (int i = 0; i < 8; ++i) {
            int fid = tid + i * THREADS;          // 0..2047 float4 slots
            int r = fid >> 5, c = (fid & 31) * 4; // 32 float4 per 128-float row
            cp_async16(Ks + r * QLD + c, kp + r * Dc + c);
            cp_async16(Vs + r * QLD + c, vp + r * Dc + c);
        }
        cp_commit();
    }

    for (int kt = 0; kt < Sc / TK; ++kt) {
        const int cur = kt & 1;
        const int nxt = cur ^ 1;

        cp_wait_all();
        __syncthreads();  // cur buffers visible; prev iter's PV reads of nxt done

        // Prefetch next K/V tile into the other buffer
        if (kt + 1 < Sc / TK) {
            const float* kp = kbase + (long long)(kt + 1) * TK * Dc;
            const float* vp = vbase + (long long)(kt + 1) * TK * Dc;
            #pragma unroll
            for (int i = 0; i < 8; ++i) {
                int fid = tid + i * THREADS;
                int r = fid >> 5, c = (fid & 31) * 4;
                cp_async16(Ks + nxt * TILE_F + r * QLD + c, kp + r * Dc + c);
                cp_async16(Vs + nxt * TILE_F + r * QLD + c, vp + r * Dc + c);
            }
            cp_commit();
        }

        const float* Kc = Ks + cur * TILE_F;
        const float* Vc = Vs + cur * TILE_F;

        // ---- Scores: S = Q * K^T (tf32 wmma; no per-fragment conversion) ----
        wmma::fragment<wmma::accumulator, 16, 16, 8, float> Sacc[2];
        wmma::fill_fragment(Sacc[0], 0.0f);
        wmma::fill_fragment(Sacc[1], 0.0f);
        #pragma unroll 4
        for (int k8 = 0; k8 < Dc / 8; ++k8) {
            wmma::fragment<wmma::matrix_a, 16, 16, 8, wmma::precision::tf32, wmma::row_major> af;
            wmma::load_matrix_sync(af, Qs + ti * 16 * QLD + k8 * 8, QLD);
            #pragma unroll
            for (int jj = 0; jj < 2; ++jj) {
                wmma::fragment<wmma::matrix_b, 16, 16, 8, wmma::precision::tf32, wmma::col_major> bf;
                wmma::load_matrix_sync(bf, Kc + (tj2 + jj) * 16 * QLD + k8 * 8, QLD);
                wmma::mma_sync(Sacc[jj], af, bf, Sacc[jj]);
            }
        }
        wmma::store_matrix_sync(Ps + ti * 16 * PLD + tj2 * 16, Sacc[0], PLD, wmma::mem_row_major);
        wmma::store_matrix_sync(Ps + ti * 16 * PLD + (tj2 + 1) * 16, Sacc[1], PLD, wmma::mem_row_major);
        __syncthreads();

        // ---- Elementwise: p = mask ? 0 : exp(s/128) via FMA polynomial ----
        {
            const int r  = tid >> 2;           // query row within tile
            const int c0 = (tid & 3) * 16;     // 16-col segment
            const float* mrow = mbase + (long long)r * Sc + kt * TK;
            float lsum = 0.0f;
            #pragma unroll
            for (int cc = 0; cc < 4; ++cc) {
                int c = c0 + cc * 4;
                float4 s4 = *(float4*)(Ps + r * PLD + c);
                float4 m4 = *(const float4*)(mrow + c);
                float4 p;
                #pragma unroll
                for (int e = 0; e < 4; ++e) {
                    float x = ((&s4.x)[e]) * 0.0078125f;
                    // degree-6 Taylor: rel err < 3e-6 for |x| <= 0.5
                    float pe = 1.388888889e-3f;                // 1/720
                    pe = fmaf(pe, x, 8.333333333e-3f);          // 1/120
                    pe = fmaf(pe, x, 4.166666667e-2f);          // 1/24
                    pe = fmaf(pe, x, 1.666666667e-1f);          // 1/6
                    pe = fmaf(pe, x, 0.5f);
                    pe = fmaf(pe, x, 1.0f);
                    pe = fmaf(pe, x, 1.0f);
                    if (fabsf(x) > 0.5f) pe = __expf(x);        // ~never taken
                    (&p.x)[e] = ((&m4.x)[e] != 0.0f) ? 0.0f : pe;
                }
                *(float4*)(Ps + r * PLD + c) = p;
                if (attnbase)
                    *(float4*)(attnbase + (long long)r * Sc + kt * TK + c) = p;
                lsum += p.x + p.y + p.z + p.w;
            }
            lsum += __shfl_xor_sync(0xffffffffu, lsum, 1);
            lsum += __shfl_xor_sync(0xffffffffu, lsum, 2);
            if ((tid & 3) == 0) lrow[r] += lsum;
        }
        __syncthreads();

        // ---- PV: O += P * V (tf32 wmma) ----
        #pragma unroll 2
        for (int k8 = 0; k8 < TK / 8; ++k8) {
            wmma::fragment<wmma::matrix_a, 16, 16, 8, wmma::precision::tf32, wmma::row_major> af;
            wmma::load_matrix_sync(af, Ps + ti * 16 * PLD + k8 * 8, PLD);
            #pragma unroll
            for (int jj = 0; jj < 4; ++jj) {
                wmma::fragment<wmma::matrix_b, 16, 16, 8, wmma::precision::tf32, wmma::row_major> bf;
                wmma::load_matrix_sync(bf, Vc + k8 * 8 * QLD + (jb + jj) * 16, QLD);
                wmma::mma_sync(Oacc[jj], af, bf, Oacc[jj]);
            }
        }
    }

    __syncthreads();
    // Stage O into smem (reuse Qs), then scaled write to gmem
    #pragma unroll
    for (int jj = 0; jj < 4; ++jj)
        wmma::store_matrix_sync(Qs + ti * 16 * QLD + (jb + jj) * 16, Oacc[jj], QLD,
                                wmma::mem_row_major);
    __syncthreads();

    {
        const int r  = tid >> 2;
        const int c0 = (tid & 3) * 32;
        const float inv = 1.0f / lrow[r];
        float* orow = outg + (bh * Sc + q0 + r) * (long long)Dc;
        #pragma unroll
        for (int cc = 0; cc < 8; ++cc) {
            int c = c0 + cc * 4;
            float4 o4 = *(float4*)(Qs + r * QLD + c);
            o4.x *= inv; o4.y *= inv; o4.z *= inv; o4.w *= inv;
            *(float4*)(orow + c) = o4;
        }
    }
}

// Kernel 2: normalize each attn row in place (re-derives the row sum).
// Measured 88.5% DRAM / 7.0 TB/s -> at roofline, leave as is.
__global__ __launch_bounds__(256, 8)
void attn_norm_kernel(float* __restrict__ attn) {
    const long long row = blockIdx.x;
    float4* rp = (float4*)(attn + row * (long long)Sc);
    const int t = threadIdx.x;

    float4 a = rp[t];
    float4 b = rp[t + 256];
    float s = a.x + a.y + a.z + a.w + b.x + b.y + b.z + b.w;
    #pragma unroll
    for (int o = 16; o > 0; o >>= 1) s += __shfl_xor_sync(0xffffffffu, s, o);

    __shared__ float red[8];
    if ((t & 31) == 0) red[t >> 5] = s;
    __syncthreads();
    float tot = red[0] + red[1] + red[2] + red[3] + red[4] + red[5] + red[6] + red[7];
    float inv = 1.0f / tot;

    a.x *= inv; a.y *= inv; a.z *= inv; a.w *= inv;
    b.x *= inv; b.y *= inv; b.z *= inv; b.w *= inv;
    rp[t] = a;
    rp[t + 256] = b;
}

extern "C" void kernel_launch(void* const* d_in, const int* in_sizes, int n_in,
                              void* d_out, int out_size) {
    const float* q = (const float*)d_in[0];
    const float* k = (const float*)d_in[1];
    const float* v = (const float*)d_in[2];
    const float* m = (const float*)d_in[3];
    float* out = (float*)d_out;

    const long long OUT_ELE = (long long)Bc * Hc * Sc * Dc;  // 16,777,216
    float* attn = ((long long)out_size > OUT_ELE) ? (out + OUT_ELE) : nullptr;

    cudaFuncSetAttribute(attn_main_kernel,
                         cudaFuncAttributeMaxDynamicSharedMemorySize, SMEM_BYTES);

    dim3 grid1(Hc, Sc / TQ, Bc);  // h fastest -> mask L2 reuse across heads
    attn_main_kernel<<<grid1, THREADS, SMEM_BYTES>>>(q, k, v, m, out, attn);

    if (attn) {
        attn_norm_kernel<<<(long long)Bc * Hc * Sc, 256>>>(attn);
    }
}